// round 1
// baseline (speedup 1.0000x reference)
#include <cuda_runtime.h>
#include <cstdint>

// Problem constants
#define N_TOK   16384
#define K_CODE  8192
#define DIM     64
#define DECAYF  0.99f
#define OMDF    0.01f          // 1 - DECAY
#define EPSF    1e-5f
#define BATCHF  32.0f

// Output layout (floats), concat of (discrete, quantized, new_count, new_weight, new_codebook)
#define OFF_DISC 0ULL
#define OFF_QUAN (134217728ULL)                 // N*K
#define OFF_CNT  (OFF_QUAN + 1048576ULL)        // + N*D
#define OFF_WGT  (OFF_CNT  + 8192ULL)           // + K
#define OFF_CB   (OFF_WGT  + 524288ULL)         // + K*D

// Scratch (device globals: allocation-free rule)
__device__ unsigned long long g_xT2[DIM * N_TOK];   // x transposed [d][t], each float duplicated into f32x2
__device__ float g_cT[DIM * K_CODE];                // codebook transposed [d][k]
__device__ float g_cnorm[K_CODE];
__device__ int   g_idx[N_TOK];
__device__ float g_count[K_CODE];
__device__ float g_sum[K_CODE * DIM];

// ---------------------------------------------------------------------------
// Prep: transpose x with per-element duplication into f32x2 pairs
__global__ void prep_x_kernel(const float* __restrict__ x) {
    int i = blockIdx.x * blockDim.x + threadIdx.x;   // over DIM*N_TOK
    if (i < DIM * N_TOK) {
        int t = i & (N_TOK - 1);
        int d = i >> 14;                              // i / N_TOK
        unsigned long long p = (unsigned long long)__float_as_uint(x[t * DIM + d]);
        g_xT2[i] = p | (p << 32);
    }
}

// Prep: transpose codebook; also zero g_sum (same size) and g_count
__global__ void prep_c_kernel(const float* __restrict__ cb) {
    int i = blockIdx.x * blockDim.x + threadIdx.x;   // over DIM*K_CODE
    if (i < DIM * K_CODE) {
        int k = i & (K_CODE - 1);
        int d = i >> 13;
        g_cT[i]  = cb[k * DIM + d];
        g_sum[i] = 0.0f;
        if (i < K_CODE) g_count[i] = 0.0f;
    }
}

// Prep: ||c||^2 per code (one warp per code)
__global__ void cnorm_kernel(const float* __restrict__ cb) {
    int w    = (blockIdx.x * blockDim.x + threadIdx.x) >> 5;
    int lane = threadIdx.x & 31;
    if (w < K_CODE) {
        float v0 = cb[w * DIM + lane];
        float v1 = cb[w * DIM + 32 + lane];
        float s = v0 * v0 + v1 * v1;
        #pragma unroll
        for (int o = 16; o; o >>= 1) s += __shfl_xor_sync(0xFFFFFFFFu, s, o);
        if (lane == 0) g_cnorm[w] = s;
    }
}

// ---------------------------------------------------------------------------
// Distance + argmin kernel.
// Tile: 128 tokens (per CTA, fixed) x 128 codes per chunk, looping all 64 chunks.
// 256 threads = 16(tx, codes) x 16(ty, tokens). Per thread: 8 tokens x 8 codes,
// accumulated as 8x4 f32x2 pairs via fma.rn.f32x2 (FFMA2, 2x fp32 throughput).
// score(k) = ||c_k||^2 - 2 * <x, c_k>  (||x||^2 omitted: constant per token).
#define TM  128
#define TKC 128
#define ARG_SMEM (65536 + 32768 + 512)

extern "C" __global__ void __launch_bounds__(256, 1)
argmin_kernel() {
    extern __shared__ unsigned char smem_raw[];
    unsigned long long* xs2 = (unsigned long long*)smem_raw;        // [64][128] dup pairs
    float* cs = (float*)(smem_raw + 65536);                         // [64][128]
    float* cn = (float*)(smem_raw + 65536 + 32768);                 // [128]

    const int tid = threadIdx.x;
    const int tx  = tid & 15;       // code group
    const int ty  = tid >> 4;       // token group
    const int t0  = blockIdx.x * TM;

    // Load token tile once (contiguous loads & stores: conflict-free)
    for (int i = tid; i < DIM * TM; i += 256)
        xs2[i] = g_xT2[((i >> 7) << 14) + t0 + (i & 127)];   // d*N_TOK + t0 + t

    float bestd[8];
    int   besti[8];
    #pragma unroll
    for (int j = 0; j < 8; j++) { bestd[j] = 3.4e38f; besti[j] = 0; }

    for (int c0 = 0; c0 < K_CODE; c0 += TKC) {
        __syncthreads();   // protect cs reuse from previous chunk's compute
        for (int i = tid; i < DIM * TKC; i += 256)
            cs[i] = g_cT[((i >> 7) << 13) + c0 + (i & 127)]; // d*K_CODE + c0 + c
        if (tid < TKC) cn[tid] = g_cnorm[c0 + tid];
        __syncthreads();

        unsigned long long acc[8][4];
        #pragma unroll
        for (int j = 0; j < 8; j++)
            #pragma unroll
            for (int p = 0; p < 4; p++) acc[j][p] = 0ULL;

        for (int d = 0; d < DIM; d++) {
            // x fragment: 8 duplicated pairs (4x LDS.128, broadcast across warp)
            const ulonglong2* xr = (const ulonglong2*)(xs2 + d * TM + ty * 8);
            unsigned long long xa[8];
            #pragma unroll
            for (int q = 0; q < 4; q++) {
                ulonglong2 v = xr[q];
                xa[2 * q] = v.x; xa[2 * q + 1] = v.y;
            }
            // c fragment: 4 natural f32x2 pairs (2x LDS.128, contiguous across warp)
            const ulonglong2* cr = (const ulonglong2*)((const unsigned long long*)(cs + d * TKC) + tx * 4);
            unsigned long long ca[4];
            {
                ulonglong2 v0 = cr[0], v1 = cr[1];
                ca[0] = v0.x; ca[1] = v0.y; ca[2] = v1.x; ca[3] = v1.y;
            }
            #pragma unroll
            for (int j = 0; j < 8; j++)
                #pragma unroll
                for (int p = 0; p < 4; p++)
                    asm("fma.rn.f32x2 %0, %1, %2, %0;"
                        : "+l"(acc[j][p]) : "l"(xa[j]), "l"(ca[p]));
        }

        // Epilogue: score + running argmin (k ascending within thread -> strict <
        // preserves first-min tie-break)
        #pragma unroll
        for (int j = 0; j < 8; j++) {
            #pragma unroll
            for (int p = 0; p < 4; p++) {
                unsigned int lo = (unsigned int)(acc[j][p]);
                unsigned int hi = (unsigned int)(acc[j][p] >> 32);
                float v0 = __uint_as_float(lo);
                float v1 = __uint_as_float(hi);
                int ci = tx * 8 + 2 * p;
                float s0 = cn[ci]     - 2.0f * v0;
                float s1 = cn[ci + 1] - 2.0f * v1;
                int k0 = c0 + ci;
                if (s0 < bestd[j]) { bestd[j] = s0; besti[j] = k0; }
                if (s1 < bestd[j]) { bestd[j] = s1; besti[j] = k0 + 1; }
            }
        }
    }

    // Cross-thread (tx) argmin reduction per token, reusing cs region
    __syncthreads();
    float* rd = cs;                   // [128][16]
    int*   ri = (int*)(cs + 128 * 16);
    #pragma unroll
    for (int j = 0; j < 8; j++) {
        rd[(ty * 8 + j) * 16 + tx] = bestd[j];
        ri[(ty * 8 + j) * 16 + tx] = besti[j];
    }
    __syncthreads();
    if (tid < TM) {
        float bd = rd[tid * 16];
        int   bi = ri[tid * 16];
        #pragma unroll
        for (int q = 1; q < 16; q++) {
            float dv = rd[tid * 16 + q];
            int   iv = ri[tid * 16 + q];
            if (dv < bd || (dv == bd && iv < bi)) { bd = dv; bi = iv; }
        }
        g_idx[t0 + tid] = bi;
    }
}

// ---------------------------------------------------------------------------
// Zero-fill the 536MB one-hot region (vectorized, grid-stride)
__global__ void fill_zero_kernel(float4* __restrict__ out, size_t n4) {
    size_t i = (size_t)blockIdx.x * blockDim.x + threadIdx.x;
    size_t stride = (size_t)gridDim.x * blockDim.x;
    float4 z = make_float4(0.f, 0.f, 0.f, 0.f);
    for (; i < n4; i += stride) out[i] = z;
}

// Scatter: one-hot ones, quantized gather, EMA accumulation atomics.
// One block per token, 64 threads (one per dim).
__global__ void scatter_kernel(const float* __restrict__ x,
                               const float* __restrict__ cb,
                               float* __restrict__ out) {
    int n = blockIdx.x;
    int d = threadIdx.x;
    int k = g_idx[n];
    float xv = x[n * DIM + d];
    out[OFF_QUAN + (size_t)n * DIM + d] = cb[k * DIM + d];
    atomicAdd(&g_sum[k * DIM + d], xv);
    if (d == 0) {
        atomicAdd(&g_count[k], 1.0f);
        out[(size_t)n * K_CODE + k] = 1.0f;
    }
}

// Finalize EMA outputs
__global__ void finalize_kernel(const float* __restrict__ ema_count,
                                const float* __restrict__ ema_weight,
                                float* __restrict__ out) {
    int i = blockIdx.x * blockDim.x + threadIdx.x;   // over K*D
    if (i < K_CODE * DIM) {
        int k = i >> 6;
        float nw = ema_weight[i] * DECAYF + g_sum[i] * OMDF;
        float nc = ema_count[k] * DECAYF + g_count[k] * OMDF;
        nc = (nc + EPSF) / (BATCHF + (float)K_CODE * EPSF) * BATCHF;
        out[OFF_WGT + i] = nw;
        out[OFF_CB  + i] = nw / nc;
        if ((i & (DIM - 1)) == 0) out[OFF_CNT + k] = nc;
    }
}

// ---------------------------------------------------------------------------
extern "C" void kernel_launch(void* const* d_in, const int* in_sizes, int n_in,
                              void* d_out, int out_size) {
    const float* x    = (const float*)d_in[0];   // [32,512,64]
    const float* cb   = (const float*)d_in[1];   // [8192,64]
    const float* ecnt = (const float*)d_in[2];   // [8192]
    const float* ewgt = (const float*)d_in[3];   // [8192,64]
    float* out = (float*)d_out;

    cudaFuncSetAttribute(argmin_kernel,
                         cudaFuncAttributeMaxDynamicSharedMemorySize, ARG_SMEM);

    prep_x_kernel<<<(DIM * N_TOK) / 256, 256>>>(x);
    prep_c_kernel<<<(DIM * K_CODE) / 256, 256>>>(cb);
    cnorm_kernel<<<(K_CODE * 32) / 256, 256>>>(cb);

    argmin_kernel<<<N_TOK / TM, 256, ARG_SMEM>>>();

    // zero-fill discrete region (N*K floats = 33554432 float4)
    fill_zero_kernel<<<16384, 256>>>((float4*)out, 33554432ULL);

    scatter_kernel<<<N_TOK, DIM>>>(x, cb, out);
    finalize_kernel<<<(K_CODE * DIM) / 256, 256>>>(ecnt, ewgt, out);
}

// round 3
// speedup vs baseline: 1.5493x; 1.5493x over previous
#include <cuda_runtime.h>
#include <cuda_bf16.h>
#include <cstdint>

// Problem constants
#define N_TOK   16384
#define K_CODE  8192
#define DIM     64
#define DECAYF  0.99f
#define OMDF    0.01f
#define EPSF    1e-5f
#define BATCHF  32.0f

// Output layout (floats): concat (discrete, quantized, new_count, new_weight, new_codebook)
#define OFF_QUAN (134217728ULL)                 // N*K
#define OFF_CNT  (OFF_QUAN + 1048576ULL)        // + N*D
#define OFF_WGT  (OFF_CNT  + 8192ULL)           // + K
#define OFF_CB   (OFF_WGT  + 524288ULL)         // + K*D

#define TOK_TILE 128
#define CHUNK    128
#define NCHUNK   64
#define CAP      384
#define THRESH   4.5f

// Scratch (device globals; allocation-free rule)
__device__ __align__(16) __nv_bfloat16 g_Abf[N_TOK * DIM];
__device__ __align__(16) __nv_bfloat16 g_Bbf[K_CODE * DIM];
__device__ float g_cnorm[K_CODE];
__device__ int   g_idx[N_TOK];
__device__ float g_count[K_CODE];
__device__ float g_sum[K_CODE * DIM];
__device__ int   g_ccnt[N_TOK];
__device__ int   g_cand[N_TOK * CAP];

// ---------------------------------------------------------------------------
__device__ __forceinline__ uint32_t smem_u32(const void* p) {
    uint32_t a;
    asm("{ .reg .u64 t; cvta.to.shared.u64 t, %1; cvt.u32.u64 %0, t; }" : "=r"(a) : "l"(p));
    return a;
}
__device__ __forceinline__ void cp_async16(uint32_t dst, const void* src) {
    asm volatile("cp.async.cg.shared.global [%0], [%1], 16;" :: "r"(dst), "l"(src) : "memory");
}
#define CP_COMMIT() asm volatile("cp.async.commit_group;" ::: "memory")
#define CP_WAIT0()  asm volatile("cp.async.wait_group 0;" ::: "memory")

__device__ __forceinline__ void ldm_x4(uint32_t& r0, uint32_t& r1, uint32_t& r2, uint32_t& r3,
                                       uint32_t addr) {
    asm volatile("ldmatrix.sync.aligned.m8n8.x4.shared.b16 {%0,%1,%2,%3}, [%4];"
                 : "=r"(r0), "=r"(r1), "=r"(r2), "=r"(r3) : "r"(addr));
}
__device__ __forceinline__ void mma16816(float* c, const uint32_t* a, uint32_t b0, uint32_t b1) {
    asm volatile("mma.sync.aligned.m16n8k16.row.col.f32.bf16.bf16.f32 "
                 "{%0,%1,%2,%3}, {%4,%5,%6,%7}, {%8,%9}, {%0,%1,%2,%3};"
                 : "+f"(c[0]), "+f"(c[1]), "+f"(c[2]), "+f"(c[3])
                 : "r"(a[0]), "r"(a[1]), "r"(a[2]), "r"(a[3]), "r"(b0), "r"(b1));
}

// ---------------------------------------------------------------------------
// Prep: bf16 conversions + zeroing
__global__ void prep_x_kernel(const float* __restrict__ x) {
    int i = blockIdx.x * blockDim.x + threadIdx.x;   // over N_TOK*DIM
    if (i < N_TOK * DIM) {
        g_Abf[i] = __float2bfloat16(x[i]);
        if (i < N_TOK) g_ccnt[i] = 0;
    }
}
__global__ void prep_c_kernel(const float* __restrict__ cb) {
    int i = blockIdx.x * blockDim.x + threadIdx.x;   // over K_CODE*DIM
    if (i < K_CODE * DIM) {
        g_Bbf[i] = __float2bfloat16(cb[i]);
        g_sum[i] = 0.0f;
        if (i < K_CODE) g_count[i] = 0.0f;
    }
}
__global__ void cnorm_kernel(const float* __restrict__ cb) {
    int w = (blockIdx.x * blockDim.x + threadIdx.x) >> 5;
    int lane = threadIdx.x & 31;
    if (w < K_CODE) {
        float v0 = cb[w * DIM + lane];
        float v1 = cb[w * DIM + 32 + lane];
        float s = v0 * v0 + v1 * v1;
        #pragma unroll
        for (int o = 16; o; o >>= 1) s += __shfl_xor_sync(0xFFFFFFFFu, s, o);
        if (lane == 0) g_cnorm[w] = s;
    }
}

// ---------------------------------------------------------------------------
// Pass 1: bf16 HMMA GEMM + approx argmin band -> candidate lists.
// 128 CTAs x 256 thr (8 warps = 4M x 2N). Warp tile 32x64. smem: A 16KB + B 2x16KB.
#define SM_B0 16384
#define P1_SMEM 49152

// swizzled smem byte offset for (row, 16B-chunk c) in a 128B-row tile
__device__ __forceinline__ uint32_t sw_off(int row, int c) {
    return (uint32_t)(row * 128 + ((c ^ (row & 7)) << 4));
}

extern "C" __global__ void __launch_bounds__(256, 1)
gemm_cand_kernel() {
    extern __shared__ unsigned char smem[];
    const uint32_t sbase = smem_u32(smem);
    const int tid   = threadIdx.x;
    const int wid   = tid >> 5;
    const int lane  = tid & 31;
    const int warpM = wid >> 1;          // 0..3
    const int warpN = wid & 1;           // 0..1
    const int g     = lane >> 2;         // row group 0..7
    const int q     = lane & 3;          // col group 0..3
    const int lr    = lane & 15;
    const int lc    = lane >> 4;
    const int tokBase = blockIdx.x * TOK_TILE + warpM * 32;

    // Prefetch B chunk 0
    {
        const char* src = (const char*)(g_Bbf) + (size_t)0 * CHUNK * 128;
        for (int j = tid; j < 1024; j += 256) {
            int row = j >> 3, c = j & 7;
            cp_async16(sbase + SM_B0 + sw_off(row, c), src + row * 128 + c * 16);
        }
        CP_COMMIT();
    }
    // Load A tile (swizzled), plain loads
    {
        const char* src = (const char*)(g_Abf) + (size_t)blockIdx.x * TOK_TILE * 128;
        for (int j = tid; j < 1024; j += 256) {
            int row = j >> 3, c = j & 7;
            float4 v = *(const float4*)(src + row * 128 + c * 16);
            *(float4*)(smem + sw_off(row, c)) = v;
        }
    }

    float rb[4] = {3.4e38f, 3.4e38f, 3.4e38f, 3.4e38f};

    for (int ci = 0; ci < NCHUNK; ci++) {
        CP_WAIT0();
        __syncthreads();
        // Prefetch next B chunk into the other buffer
        if (ci + 1 < NCHUNK) {
            const char* src = (const char*)(g_Bbf) + (size_t)(ci + 1) * CHUNK * 128;
            uint32_t bb = sbase + SM_B0 + ((ci + 1) & 1) * 16384;
            for (int j = tid; j < 1024; j += 256) {
                int row = j >> 3, c = j & 7;
                cp_async16(bb + sw_off(row, c), src + row * 128 + c * 16);
            }
            CP_COMMIT();
        }

        const uint32_t As = sbase;
        const uint32_t Bs = sbase + SM_B0 + (ci & 1) * 16384;

        float acc[2][8][4];
        #pragma unroll
        for (int mi = 0; mi < 2; mi++)
            #pragma unroll
            for (int ni = 0; ni < 8; ni++)
                #pragma unroll
                for (int t = 0; t < 4; t++) acc[mi][ni][t] = 0.0f;

        #pragma unroll
        for (int ks = 0; ks < 4; ks++) {
            uint32_t a[2][4];
            #pragma unroll
            for (int mi = 0; mi < 2; mi++) {
                int row = warpM * 32 + mi * 16 + lr;
                ldm_x4(a[mi][0], a[mi][1], a[mi][2], a[mi][3],
                       As + sw_off(row, ks * 2 + lc));
            }
            uint32_t b[4][4];
            #pragma unroll
            for (int nt = 0; nt < 4; nt++) {
                int row = warpN * 64 + nt * 16 + lr;
                ldm_x4(b[nt][0], b[nt][1], b[nt][2], b[nt][3],
                       Bs + sw_off(row, ks * 2 + lc));
            }
            #pragma unroll
            for (int mi = 0; mi < 2; mi++)
                #pragma unroll
                for (int ni = 0; ni < 8; ni++) {
                    int nt = ni >> 1, od = ni & 1;
                    mma16816(acc[mi][ni], a[mi], b[nt][od], b[nt][od + 2]);
                }
        }

        // scores: s = cnorm - 2*dot (in place)
        float2 cn[8];
        #pragma unroll
        for (int ni = 0; ni < 8; ni++) {
            int col = ci * CHUNK + warpN * 64 + ni * 8 + q * 2;
            cn[ni] = __ldg((const float2*)(g_cnorm + col));
        }
        #pragma unroll
        for (int mi = 0; mi < 2; mi++)
            #pragma unroll
            for (int ni = 0; ni < 8; ni++) {
                acc[mi][ni][0] = fmaf(-2.0f, acc[mi][ni][0], cn[ni].x);
                acc[mi][ni][1] = fmaf(-2.0f, acc[mi][ni][1], cn[ni].y);
                acc[mi][ni][2] = fmaf(-2.0f, acc[mi][ni][2], cn[ni].x);
                acc[mi][ni][3] = fmaf(-2.0f, acc[mi][ni][3], cn[ni].y);
            }

        // per-row chunk min (across q lanes), running best, candidate appends
        #pragma unroll
        for (int mi = 0; mi < 2; mi++) {
            #pragma unroll
            for (int h = 0; h < 2; h++) {
                float cm = 3.4e38f;
                #pragma unroll
                for (int ni = 0; ni < 8; ni++)
                    cm = fminf(cm, fminf(acc[mi][ni][2 * h], acc[mi][ni][2 * h + 1]));
                cm = fminf(cm, __shfl_xor_sync(0xFFFFFFFFu, cm, 1));
                cm = fminf(cm, __shfl_xor_sync(0xFFFFFFFFu, cm, 2));
                float rbv = fminf(rb[mi * 2 + h], cm);
                rb[mi * 2 + h] = rbv;
                float lim = rbv + THRESH;
                int tok = tokBase + mi * 16 + h * 8 + g;
                #pragma unroll
                for (int ni = 0; ni < 8; ni++) {
                    int k0 = ci * CHUNK + warpN * 64 + ni * 8 + q * 2;
                    float s0 = acc[mi][ni][2 * h], s1 = acc[mi][ni][2 * h + 1];
                    if (s0 < lim) {
                        int sl = atomicAdd(&g_ccnt[tok], 1);
                        if (sl < CAP) g_cand[tok * CAP + sl] = k0;
                    }
                    if (s1 < lim) {
                        int sl = atomicAdd(&g_ccnt[tok], 1);
                        if (sl < CAP) g_cand[tok * CAP + sl] = k0 + 1;
                    }
                }
            }
        }
        __syncthreads();   // all reads of B buffer done before next overwrite
    }
}

// ---------------------------------------------------------------------------
// Pass 2: exact fp32 refine over candidates (one warp per token)
__global__ void __launch_bounds__(256)
refine_kernel(const float* __restrict__ x, const float* __restrict__ cb) {
    __shared__ float sx[8][64];
    const int wid = threadIdx.x >> 5, lane = threadIdx.x & 31;
    const int tok = blockIdx.x * 8 + wid;
    sx[wid][lane]      = x[tok * DIM + lane];
    sx[wid][lane + 32] = x[tok * DIM + 32 + lane];
    __syncwarp();

    int cnt = g_ccnt[tok];
    float bd = 3.4e38f;
    int   bi = 0x7fffffff;

    if (cnt <= CAP) {
        for (int i = lane; i < cnt; i += 32) {
            int k = g_cand[tok * CAP + i];
            const float4* cr = (const float4*)(cb + k * DIM);
            float a = 0.0f;
            #pragma unroll
            for (int j = 0; j < 16; j++) {
                float4 c4 = __ldg(cr + j);
                a = fmaf(sx[wid][4 * j],     c4.x, a);
                a = fmaf(sx[wid][4 * j + 1], c4.y, a);
                a = fmaf(sx[wid][4 * j + 2], c4.z, a);
                a = fmaf(sx[wid][4 * j + 3], c4.w, a);
            }
            float d = fmaf(-2.0f, a, g_cnorm[k]);
            if (d < bd || (d == bd && k < bi)) { bd = d; bi = k; }
        }
    } else {
        for (int k = lane; k < K_CODE; k += 32) {
            const float4* cr = (const float4*)(cb + k * DIM);
            float a = 0.0f;
            #pragma unroll
            for (int j = 0; j < 16; j++) {
                float4 c4 = __ldg(cr + j);
                a = fmaf(sx[wid][4 * j],     c4.x, a);
                a = fmaf(sx[wid][4 * j + 1], c4.y, a);
                a = fmaf(sx[wid][4 * j + 2], c4.z, a);
                a = fmaf(sx[wid][4 * j + 3], c4.w, a);
            }
            float d = fmaf(-2.0f, a, g_cnorm[k]);
            if (d < bd || (d == bd && k < bi)) { bd = d; bi = k; }
        }
    }
    #pragma unroll
    for (int off = 16; off; off >>= 1) {
        float od = __shfl_xor_sync(0xFFFFFFFFu, bd, off);
        int   oi = __shfl_xor_sync(0xFFFFFFFFu, bi, off);
        if (od < bd || (od == bd && oi < bi)) { bd = od; bi = oi; }
    }
    if (lane == 0) g_idx[tok] = bi;
}

// ---------------------------------------------------------------------------
__global__ void fill_zero_kernel(float4* __restrict__ out, size_t n4) {
    size_t i = (size_t)blockIdx.x * blockDim.x + threadIdx.x;
    size_t stride = (size_t)gridDim.x * blockDim.x;
    float4 z = make_float4(0.f, 0.f, 0.f, 0.f);
    for (; i < n4; i += stride) out[i] = z;
}

__global__ void scatter_kernel(const float* __restrict__ x,
                               const float* __restrict__ cb,
                               float* __restrict__ out) {
    int n = blockIdx.x;
    int d = threadIdx.x;
    int k = g_idx[n];
    float xv = x[n * DIM + d];
    out[OFF_QUAN + (size_t)n * DIM + d] = cb[k * DIM + d];
    atomicAdd(&g_sum[k * DIM + d], xv);
    if (d == 0) {
        atomicAdd(&g_count[k], 1.0f);
        out[(size_t)n * K_CODE + k] = 1.0f;
    }
}

__global__ void finalize_kernel(const float* __restrict__ ema_count,
                                const float* __restrict__ ema_weight,
                                float* __restrict__ out) {
    int i = blockIdx.x * blockDim.x + threadIdx.x;
    if (i < K_CODE * DIM) {
        int k = i >> 6;
        float nw = ema_weight[i] * DECAYF + g_sum[i] * OMDF;
        float nc = ema_count[k] * DECAYF + g_count[k] * OMDF;
        nc = (nc + EPSF) / (BATCHF + (float)K_CODE * EPSF) * BATCHF;
        out[OFF_WGT + i] = nw;
        out[OFF_CB  + i] = nw / nc;
        if ((i & (DIM - 1)) == 0) out[OFF_CNT + k] = nc;
    }
}

// ---------------------------------------------------------------------------
extern "C" void kernel_launch(void* const* d_in, const int* in_sizes, int n_in,
                              void* d_out, int out_size) {
    const float* x    = (const float*)d_in[0];
    const float* cb   = (const float*)d_in[1];
    const float* ecnt = (const float*)d_in[2];
    const float* ewgt = (const float*)d_in[3];
    float* out = (float*)d_out;

    cudaFuncSetAttribute(gemm_cand_kernel,
                         cudaFuncAttributeMaxDynamicSharedMemorySize, P1_SMEM);

    prep_x_kernel<<<(N_TOK * DIM) / 256, 256>>>(x);
    prep_c_kernel<<<(K_CODE * DIM) / 256, 256>>>(cb);
    cnorm_kernel<<<(K_CODE * 32) / 256, 256>>>(cb);

    gemm_cand_kernel<<<N_TOK / TOK_TILE, 256, P1_SMEM>>>();
    refine_kernel<<<N_TOK / 8, 256>>>(x, cb);

    fill_zero_kernel<<<16384, 256>>>((float4*)out, 33554432ULL);
    scatter_kernel<<<N_TOK, DIM>>>(x, cb, out);
    finalize_kernel<<<(K_CODE * DIM) / 256, 256>>>(ecnt, ewgt, out);
}

// round 5
// speedup vs baseline: 1.5854x; 1.0233x over previous
#include <cuda_runtime.h>
#include <cuda_bf16.h>
#include <cstdint>

// Problem constants
#define N_TOK   16384
#define K_CODE  8192
#define DIM     64
#define DECAYF  0.99f
#define OMDF    0.01f
#define EPSF    1e-5f
#define BATCHF  32.0f

// Output layout (floats): concat (discrete, quantized, new_count, new_weight, new_codebook)
#define OFF_QUAN (134217728ULL)                 // N*K
#define OFF_CNT  (OFF_QUAN + 1048576ULL)        // + N*D
#define OFF_WGT  (OFF_CNT  + 8192ULL)           // + K
#define OFF_CB   (OFF_WGT  + 524288ULL)         // + K*D

#define TOK_TILE 128
#define CHUNK    128
#define NCHUNK   64
#define CAP      384
#define THRESH   4.5f

// Scratch (device globals; allocation-free rule)
__device__ __align__(16) __nv_bfloat16 g_Abf[N_TOK * DIM];
__device__ __align__(16) __nv_bfloat16 g_Bbf[K_CODE * DIM];
__device__ float g_cnorm[K_CODE];
__device__ int   g_idx[N_TOK];
__device__ float g_count[K_CODE];
__device__ float g_sum[K_CODE * DIM];
__device__ int   g_ccnt[N_TOK];
__device__ int   g_cand[N_TOK * CAP];

// ---------------------------------------------------------------------------
__device__ __forceinline__ uint32_t smem_u32(const void* p) {
    uint32_t a;
    asm("{ .reg .u64 t; cvta.to.shared.u64 t, %1; cvt.u32.u64 %0, t; }" : "=r"(a) : "l"(p));
    return a;
}
__device__ __forceinline__ void cp_async16(uint32_t dst, const void* src) {
    asm volatile("cp.async.cg.shared.global [%0], [%1], 16;" :: "r"(dst), "l"(src) : "memory");
}
#define CP_COMMIT() asm volatile("cp.async.commit_group;" ::: "memory")
#define CP_WAIT(n)  asm volatile("cp.async.wait_group %0;" :: "n"(n) : "memory")

__device__ __forceinline__ void ldm_x4(uint32_t& r0, uint32_t& r1, uint32_t& r2, uint32_t& r3,
                                       uint32_t addr) {
    asm volatile("ldmatrix.sync.aligned.m8n8.x4.shared.b16 {%0,%1,%2,%3}, [%4];"
                 : "=r"(r0), "=r"(r1), "=r"(r2), "=r"(r3) : "r"(addr));
}
__device__ __forceinline__ void mma16816(float* c, const uint32_t* a, uint32_t b0, uint32_t b1) {
    asm volatile("mma.sync.aligned.m16n8k16.row.col.f32.bf16.bf16.f32 "
                 "{%0,%1,%2,%3}, {%4,%5,%6,%7}, {%8,%9}, {%0,%1,%2,%3};"
                 : "+f"(c[0]), "+f"(c[1]), "+f"(c[2]), "+f"(c[3])
                 : "r"(a[0]), "r"(a[1]), "r"(a[2]), "r"(a[3]), "r"(b0), "r"(b1));
}

// ---------------------------------------------------------------------------
// Prep kernels
__global__ void prep_x_kernel(const float* __restrict__ x) {
    int i = blockIdx.x * blockDim.x + threadIdx.x;
    if (i < N_TOK * DIM) {
        g_Abf[i] = __float2bfloat16(x[i]);
        if (i < N_TOK) g_ccnt[i] = 0;
    }
}
__global__ void prep_c_kernel(const float* __restrict__ cb) {
    int i = blockIdx.x * blockDim.x + threadIdx.x;
    if (i < K_CODE * DIM) {
        g_Bbf[i] = __float2bfloat16(cb[i]);
        g_sum[i] = 0.0f;
        if (i < K_CODE) g_count[i] = 0.0f;
    }
}
__global__ void cnorm_kernel(const float* __restrict__ cb) {
    int w = (blockIdx.x * blockDim.x + threadIdx.x) >> 5;
    int lane = threadIdx.x & 31;
    if (w < K_CODE) {
        float v0 = cb[w * DIM + lane];
        float v1 = cb[w * DIM + 32 + lane];
        float s = v0 * v0 + v1 * v1;
        #pragma unroll
        for (int o = 16; o; o >>= 1) s += __shfl_xor_sync(0xFFFFFFFFu, s, o);
        if (lane == 0) g_cnorm[w] = s;
    }
}

// ---------------------------------------------------------------------------
// Pass 1: bf16 HMMA GEMM + approx argmin band -> candidate lists.
// 128 CTAs x 512 thr (16 warps = 4M x 4N). Warp tile 32x32.
// smem: A 16KB @0, B 3-stage ring @16384 (3 x 16KB).
#define SM_B0   16384
#define P1_SMEM 65536

__device__ __forceinline__ uint32_t sw_off(int row, int c) {
    return (uint32_t)(row * 128 + ((c ^ (row & 7)) << 4));
}

__device__ __forceinline__ void prefetch_B(uint32_t bb, int ci, int tid) {
    const char* src = (const char*)(g_Bbf) + (size_t)ci * CHUNK * 128;
    for (int j = tid; j < 1024; j += 512) {
        int row = j >> 3, c = j & 7;
        cp_async16(bb + sw_off(row, c), src + row * 128 + c * 16);
    }
    CP_COMMIT();
}

extern "C" __global__ void __launch_bounds__(512, 1)
gemm_cand_kernel() {
    extern __shared__ unsigned char smem[];
    const uint32_t sbase = smem_u32(smem);
    const int tid   = threadIdx.x;
    const int wid   = tid >> 5;
    const int lane  = tid & 31;
    const int warpM = wid >> 2;          // 0..3
    const int warpN = wid & 3;           // 0..3
    const int g     = lane >> 2;         // row group 0..7
    const int q     = lane & 3;          // col group 0..3
    const int lr    = lane & 15;
    const int lc    = lane >> 4;
    const int tokBase = blockIdx.x * TOK_TILE + warpM * 32;

    // Prolog: prefetch B chunks 0 and 1
    prefetch_B(sbase + SM_B0,         0, tid);
    prefetch_B(sbase + SM_B0 + 16384, 1, tid);

    // Load A tile (swizzled), plain loads
    {
        const char* src = (const char*)(g_Abf) + (size_t)blockIdx.x * TOK_TILE * 128;
        for (int j = tid; j < 1024; j += 512) {
            int row = j >> 3, c = j & 7;
            float4 v = *(const float4*)(src + row * 128 + c * 16);
            *(float4*)(smem + sw_off(row, c)) = v;
        }
    }

    float rb[4] = {3.4e38f, 3.4e38f, 3.4e38f, 3.4e38f};

    for (int ci = 0; ci < NCHUNK; ci++) {
        if (ci + 1 < NCHUNK) { CP_WAIT(1); } else { CP_WAIT(0); }
        __syncthreads();   // chunk ci data ready; all warps done reading buf (ci+2)%3

        if (ci + 2 < NCHUNK)
            prefetch_B(sbase + SM_B0 + ((ci + 2) % 3) * 16384, ci + 2, tid);

        const uint32_t As = sbase;
        const uint32_t Bs = sbase + SM_B0 + (ci % 3) * 16384;

        float acc[2][4][4];
        #pragma unroll
        for (int mi = 0; mi < 2; mi++)
            #pragma unroll
            for (int ni = 0; ni < 4; ni++)
                #pragma unroll
                for (int t = 0; t < 4; t++) acc[mi][ni][t] = 0.0f;

        #pragma unroll
        for (int ks = 0; ks < 4; ks++) {
            uint32_t a[2][4];
            #pragma unroll
            for (int mi = 0; mi < 2; mi++) {
                int row = warpM * 32 + mi * 16 + lr;
                ldm_x4(a[mi][0], a[mi][1], a[mi][2], a[mi][3],
                       As + sw_off(row, ks * 2 + lc));
            }
            uint32_t b[2][4];
            #pragma unroll
            for (int nt = 0; nt < 2; nt++) {
                int row = warpN * 32 + nt * 16 + lr;
                ldm_x4(b[nt][0], b[nt][1], b[nt][2], b[nt][3],
                       Bs + sw_off(row, ks * 2 + lc));
            }
            #pragma unroll
            for (int mi = 0; mi < 2; mi++)
                #pragma unroll
                for (int ni = 0; ni < 4; ni++) {
                    int nt = ni >> 1, od = ni & 1;
                    mma16816(acc[mi][ni], a[mi], b[nt][od], b[nt][od + 2]);
                }
        }

        // scores: s = cnorm - 2*dot
        float2 cn[4];
        #pragma unroll
        for (int ni = 0; ni < 4; ni++) {
            int col = ci * CHUNK + warpN * 32 + ni * 8 + q * 2;
            cn[ni] = __ldg((const float2*)(g_cnorm + col));
        }
        #pragma unroll
        for (int mi = 0; mi < 2; mi++)
            #pragma unroll
            for (int ni = 0; ni < 4; ni++) {
                acc[mi][ni][0] = fmaf(-2.0f, acc[mi][ni][0], cn[ni].x);
                acc[mi][ni][1] = fmaf(-2.0f, acc[mi][ni][1], cn[ni].y);
                acc[mi][ni][2] = fmaf(-2.0f, acc[mi][ni][2], cn[ni].x);
                acc[mi][ni][3] = fmaf(-2.0f, acc[mi][ni][3], cn[ni].y);
            }

        // per-row chunk min, running best, conditional candidate appends
        #pragma unroll
        for (int mi = 0; mi < 2; mi++) {
            #pragma unroll
            for (int h = 0; h < 2; h++) {
                float cm = 3.4e38f;
                #pragma unroll
                for (int ni = 0; ni < 4; ni++)
                    cm = fminf(cm, fminf(acc[mi][ni][2 * h], acc[mi][ni][2 * h + 1]));
                cm = fminf(cm, __shfl_xor_sync(0xFFFFFFFFu, cm, 1));
                cm = fminf(cm, __shfl_xor_sync(0xFFFFFFFFu, cm, 2));
                float rbv = fminf(rb[mi * 2 + h], cm);
                rb[mi * 2 + h] = rbv;
                float lim = rbv + THRESH;
                if (__any_sync(0xFFFFFFFFu, cm < lim)) {
                    int tok = tokBase + mi * 16 + h * 8 + g;
                    #pragma unroll
                    for (int ni = 0; ni < 4; ni++) {
                        int k0 = ci * CHUNK + warpN * 32 + ni * 8 + q * 2;
                        float s0 = acc[mi][ni][2 * h], s1 = acc[mi][ni][2 * h + 1];
                        if (s0 < lim) {
                            int sl = atomicAdd(&g_ccnt[tok], 1);
                            if (sl < CAP) g_cand[tok * CAP + sl] = k0;
                        }
                        if (s1 < lim) {
                            int sl = atomicAdd(&g_ccnt[tok], 1);
                            if (sl < CAP) g_cand[tok * CAP + sl] = k0 + 1;
                        }
                    }
                }
            }
        }
    }
}

// ---------------------------------------------------------------------------
// Pass 2: exact fp32 refine over candidates (one warp per token)
__global__ void __launch_bounds__(256)
refine_kernel(const float* __restrict__ x, const float* __restrict__ cb) {
    __shared__ float sx[8][64];
    const int wid = threadIdx.x >> 5, lane = threadIdx.x & 31;
    const int tok = blockIdx.x * 8 + wid;
    sx[wid][lane]      = x[tok * DIM + lane];
    sx[wid][lane + 32] = x[tok * DIM + 32 + lane];
    __syncwarp();

    int cnt = g_ccnt[tok];
    float bd = 3.4e38f;
    int   bi = 0x7fffffff;

    if (cnt <= CAP) {
        for (int i = lane; i < cnt; i += 32) {
            int k = g_cand[tok * CAP + i];
            const float4* cr = (const float4*)(cb + k * DIM);
            float a = 0.0f;
            #pragma unroll
            for (int j = 0; j < 16; j++) {
                float4 c4 = __ldg(cr + j);
                a = fmaf(sx[wid][4 * j],     c4.x, a);
                a = fmaf(sx[wid][4 * j + 1], c4.y, a);
                a = fmaf(sx[wid][4 * j + 2], c4.z, a);
                a = fmaf(sx[wid][4 * j + 3], c4.w, a);
            }
            float d = fmaf(-2.0f, a, g_cnorm[k]);
            if (d < bd || (d == bd && k < bi)) { bd = d; bi = k; }
        }
    } else {
        for (int k = lane; k < K_CODE; k += 32) {
            const float4* cr = (const float4*)(cb + k * DIM);
            float a = 0.0f;
            #pragma unroll
            for (int j = 0; j < 16; j++) {
                float4 c4 = __ldg(cr + j);
                a = fmaf(sx[wid][4 * j],     c4.x, a);
                a = fmaf(sx[wid][4 * j + 1], c4.y, a);
                a = fmaf(sx[wid][4 * j + 2], c4.z, a);
                a = fmaf(sx[wid][4 * j + 3], c4.w, a);
            }
            float d = fmaf(-2.0f, a, g_cnorm[k]);
            if (d < bd || (d == bd && k < bi)) { bd = d; bi = k; }
        }
    }
    #pragma unroll
    for (int off = 16; off; off >>= 1) {
        float od = __shfl_xor_sync(0xFFFFFFFFu, bd, off);
        int   oi = __shfl_xor_sync(0xFFFFFFFFu, bi, off);
        if (od < bd || (od == bd && oi < bi)) { bd = od; bi = oi; }
    }
    if (lane == 0) g_idx[tok] = bi;
}

// ---------------------------------------------------------------------------
__global__ void fill_zero_kernel(float4* __restrict__ out, size_t n4) {
    size_t i = (size_t)blockIdx.x * blockDim.x + threadIdx.x;
    size_t stride = (size_t)gridDim.x * blockDim.x;
    float4 z = make_float4(0.f, 0.f, 0.f, 0.f);
    for (; i < n4; i += stride) out[i] = z;
}

__global__ void scatter_kernel(const float* __restrict__ x,
                               const float* __restrict__ cb,
                               float* __restrict__ out) {
    int n = blockIdx.x;
    int d = threadIdx.x;
    int k = g_idx[n];
    float xv = x[n * DIM + d];
    out[OFF_QUAN + (size_t)n * DIM + d] = cb[k * DIM + d];
    atomicAdd(&g_sum[k * DIM + d], xv);
    if (d == 0) {
        atomicAdd(&g_count[k], 1.0f);
        out[(size_t)n * K_CODE + k] = 1.0f;
    }
}

__global__ void finalize_kernel(const float* __restrict__ ema_count,
                                const float* __restrict__ ema_weight,
                                float* __restrict__ out) {
    int i = blockIdx.x * blockDim.x + threadIdx.x;
    if (i < K_CODE * DIM) {
        int k = i >> 6;
        float nw = ema_weight[i] * DECAYF + g_sum[i] * OMDF;
        float nc = ema_count[k] * DECAYF + g_count[k] * OMDF;
        nc = (nc + EPSF) / (BATCHF + (float)K_CODE * EPSF) * BATCHF;
        out[OFF_WGT + i] = nw;
        out[OFF_CB  + i] = nw / nc;
        if ((i & (DIM - 1)) == 0) out[OFF_CNT + k] = nc;
    }
}

// ---------------------------------------------------------------------------
extern "C" void kernel_launch(void* const* d_in, const int* in_sizes, int n_in,
                              void* d_out, int out_size) {
    const float* x    = (const float*)d_in[0];
    const float* cb   = (const float*)d_in[1];
    const float* ecnt = (const float*)d_in[2];
    const float* ewgt = (const float*)d_in[3];
    float* out = (float*)d_out;

    // One-time side stream + events for overlapping the big zero-fill with the
    // GEMM (fork/join via events: capture-legal; created on the first,
    // non-captured correctness call and reused identically every call).
    static cudaStream_t s_side = nullptr;
    static cudaEvent_t  s_fork = nullptr, s_join = nullptr;
    if (s_side == nullptr) {
        cudaStreamCreateWithFlags(&s_side, cudaStreamNonBlocking);
        cudaEventCreateWithFlags(&s_fork, cudaEventDisableTiming);
        cudaEventCreateWithFlags(&s_join, cudaEventDisableTiming);
    }

    cudaFuncSetAttribute(gemm_cand_kernel,
                         cudaFuncAttributeMaxDynamicSharedMemorySize, P1_SMEM);

    // Fork: zero-fill of the 536MB one-hot region runs on the side stream
    cudaEventRecord(s_fork, 0);
    cudaStreamWaitEvent(s_side, s_fork, 0);
    fill_zero_kernel<<<16384, 256, 0, s_side>>>((float4*)out, 33554432ULL);
    cudaEventRecord(s_join, s_side);

    // Main path
    prep_x_kernel<<<(N_TOK * DIM) / 256, 256>>>(x);
    prep_c_kernel<<<(K_CODE * DIM) / 256, 256>>>(cb);
    cnorm_kernel<<<(K_CODE * 32) / 256, 256>>>(cb);

    gemm_cand_kernel<<<N_TOK / TOK_TILE, 512, P1_SMEM>>>();
    refine_kernel<<<N_TOK / 8, 256>>>(x, cb);

    // Join: scatter writes into the zero-filled region
    cudaStreamWaitEvent(0, s_join, 0);
    scatter_kernel<<<N_TOK, DIM>>>(x, cb, out);
    finalize_kernel<<<(K_CODE * DIM) / 256, 256>>>(ecnt, ewgt, out);
}

// round 6
// speedup vs baseline: 1.7524x; 1.1053x over previous
#include <cuda_runtime.h>
#include <cuda_bf16.h>
#include <cstdint>

// Problem constants
#define N_TOK   16384
#define K_CODE  8192
#define DIM     64
#define DECAYF  0.99f
#define OMDF    0.01f
#define EPSF    1e-5f
#define BATCHF  32.0f

// Output layout (floats): concat (discrete, quantized, new_count, new_weight, new_codebook)
#define OFF_QUAN (134217728ULL)                 // N*K
#define OFF_CNT  (OFF_QUAN + 1048576ULL)        // + N*D
#define OFF_WGT  (OFF_CNT  + 8192ULL)           // + K
#define OFF_CB   (OFF_WGT  + 524288ULL)         // + K*D

#define TOK_TILE 128
#define CHUNK    64
#define KSPLIT   2
#define KSLICE   (K_CODE / KSPLIT)              // 4096
#define NCHUNK   (KSLICE / CHUNK)               // 64
#define CAP      384
#define THRESH   4.5f

// Scratch (device globals; allocation-free rule)
__device__ __align__(16) __nv_bfloat16 g_Abf[N_TOK * DIM];
__device__ __align__(16) __nv_bfloat16 g_Bbf[K_CODE * DIM];
__device__ float g_cnorm[K_CODE];
__device__ int   g_idx[N_TOK];
__device__ float g_count[K_CODE];
__device__ float g_sum[K_CODE * DIM];
__device__ int   g_ccnt[N_TOK];
__device__ int   g_cand[N_TOK * CAP];

// ---------------------------------------------------------------------------
__device__ __forceinline__ uint32_t smem_u32(const void* p) {
    uint32_t a;
    asm("{ .reg .u64 t; cvta.to.shared.u64 t, %1; cvt.u32.u64 %0, t; }" : "=r"(a) : "l"(p));
    return a;
}
__device__ __forceinline__ void cp_async16(uint32_t dst, const void* src) {
    asm volatile("cp.async.cg.shared.global [%0], [%1], 16;" :: "r"(dst), "l"(src) : "memory");
}
#define CP_COMMIT() asm volatile("cp.async.commit_group;" ::: "memory")
#define CP_WAIT(n)  asm volatile("cp.async.wait_group %0;" :: "n"(n) : "memory")

__device__ __forceinline__ void ldm_x4(uint32_t& r0, uint32_t& r1, uint32_t& r2, uint32_t& r3,
                                       uint32_t addr) {
    asm volatile("ldmatrix.sync.aligned.m8n8.x4.shared.b16 {%0,%1,%2,%3}, [%4];"
                 : "=r"(r0), "=r"(r1), "=r"(r2), "=r"(r3) : "r"(addr));
}
__device__ __forceinline__ void mma16816(float* c, const uint32_t* a, uint32_t b0, uint32_t b1) {
    asm volatile("mma.sync.aligned.m16n8k16.row.col.f32.bf16.bf16.f32 "
                 "{%0,%1,%2,%3}, {%4,%5,%6,%7}, {%8,%9}, {%0,%1,%2,%3};"
                 : "+f"(c[0]), "+f"(c[1]), "+f"(c[2]), "+f"(c[3])
                 : "r"(a[0]), "r"(a[1]), "r"(a[2]), "r"(a[3]), "r"(b0), "r"(b1));
}

// ---------------------------------------------------------------------------
// Prep kernels
__global__ void prep_x_kernel(const float* __restrict__ x) {
    int i = blockIdx.x * blockDim.x + threadIdx.x;
    if (i < N_TOK * DIM) {
        g_Abf[i] = __float2bfloat16(x[i]);
        if (i < N_TOK) g_ccnt[i] = 0;
    }
}
__global__ void prep_c_kernel(const float* __restrict__ cb) {
    int i = blockIdx.x * blockDim.x + threadIdx.x;
    if (i < K_CODE * DIM) {
        g_Bbf[i] = __float2bfloat16(cb[i]);
        g_sum[i] = 0.0f;
        if (i < K_CODE) g_count[i] = 0.0f;
    }
}
__global__ void cnorm_kernel(const float* __restrict__ cb) {
    int w = (blockIdx.x * blockDim.x + threadIdx.x) >> 5;
    int lane = threadIdx.x & 31;
    if (w < K_CODE) {
        float v0 = cb[w * DIM + lane];
        float v1 = cb[w * DIM + 32 + lane];
        float s = v0 * v0 + v1 * v1;
        #pragma unroll
        for (int o = 16; o; o >>= 1) s += __shfl_xor_sync(0xFFFFFFFFu, s, o);
        if (lane == 0) g_cnorm[w] = s;
    }
}

// ---------------------------------------------------------------------------
// Pass 1: bf16 HMMA GEMM + approx argmin band -> candidate lists.
// Grid = 128 token-blocks x 2 K-slices = 256 CTAs, 256 thr (8 warps = 4M x 2N).
// Warp tile 32x32. smem: A 16KB @0, B 3-stage ring @16384 (3 x 8KB) = 40KB -> 2 CTAs/SM.
#define SM_B0   16384
#define B_TILE  8192
#define P1_SMEM (SM_B0 + 3 * B_TILE)

__device__ __forceinline__ uint32_t sw_off(int row, int c) {
    return (uint32_t)(row * 128 + ((c ^ (row & 7)) << 4));
}

__device__ __forceinline__ void prefetch_B(uint32_t bb, int kbase_rows, int tid) {
    const char* src = (const char*)(g_Bbf) + (size_t)kbase_rows * 128;
    #pragma unroll
    for (int j = tid; j < 512; j += 256) {
        int row = j >> 3, c = j & 7;
        cp_async16(bb + sw_off(row, c), src + row * 128 + c * 16);
    }
    CP_COMMIT();
}

extern "C" __global__ void __launch_bounds__(256, 2)
gemm_cand_kernel() {
    extern __shared__ unsigned char smem[];
    const uint32_t sbase = smem_u32(smem);
    const int tid   = threadIdx.x;
    const int wid   = tid >> 5;
    const int lane  = tid & 31;
    const int warpM = wid >> 1;          // 0..3
    const int warpN = wid & 1;           // 0..1
    const int g     = lane >> 2;         // row group 0..7
    const int q     = lane & 3;          // col group 0..3
    const int lr    = lane & 15;
    const int lc    = lane >> 4;
    const int tb    = blockIdx.x & 127;             // token block
    const int slice = blockIdx.x >> 7;              // k slice 0..1
    const int kslice0 = slice * KSLICE;
    const int tokBase = tb * TOK_TILE + warpM * 32;

    // Prolog: prefetch B chunks 0 and 1 of this slice
    prefetch_B(sbase + SM_B0,          kslice0,          tid);
    prefetch_B(sbase + SM_B0 + B_TILE, kslice0 + CHUNK,  tid);

    // Load A tile (swizzled), plain loads
    {
        const char* src = (const char*)(g_Abf) + (size_t)tb * TOK_TILE * 128;
        for (int j = tid; j < 1024; j += 256) {
            int row = j >> 3, c = j & 7;
            float4 v = *(const float4*)(src + row * 128 + c * 16);
            *(float4*)(smem + sw_off(row, c)) = v;
        }
    }

    float rb[4] = {3.4e38f, 3.4e38f, 3.4e38f, 3.4e38f};

    for (int ci = 0; ci < NCHUNK; ci++) {
        if (ci + 1 < NCHUNK) { CP_WAIT(1); } else { CP_WAIT(0); }
        __syncthreads();   // chunk ci ready; all warps done with buf (ci+2)%3

        if (ci + 2 < NCHUNK)
            prefetch_B(sbase + SM_B0 + ((ci + 2) % 3) * B_TILE,
                       kslice0 + (ci + 2) * CHUNK, tid);

        const uint32_t As = sbase;
        const uint32_t Bs = sbase + SM_B0 + (ci % 3) * B_TILE;

        float acc[2][4][4];
        #pragma unroll
        for (int mi = 0; mi < 2; mi++)
            #pragma unroll
            for (int ni = 0; ni < 4; ni++)
                #pragma unroll
                for (int t = 0; t < 4; t++) acc[mi][ni][t] = 0.0f;

        #pragma unroll
        for (int ks = 0; ks < 4; ks++) {
            uint32_t a[2][4];
            #pragma unroll
            for (int mi = 0; mi < 2; mi++) {
                int row = warpM * 32 + mi * 16 + lr;
                ldm_x4(a[mi][0], a[mi][1], a[mi][2], a[mi][3],
                       As + sw_off(row, ks * 2 + lc));
            }
            uint32_t b[2][4];
            #pragma unroll
            for (int nt = 0; nt < 2; nt++) {
                int row = warpN * 32 + nt * 16 + lr;
                ldm_x4(b[nt][0], b[nt][1], b[nt][2], b[nt][3],
                       Bs + sw_off(row, ks * 2 + lc));
            }
            #pragma unroll
            for (int mi = 0; mi < 2; mi++)
                #pragma unroll
                for (int ni = 0; ni < 4; ni++) {
                    int nt = ni >> 1, od = ni & 1;
                    mma16816(acc[mi][ni], a[mi], b[nt][od], b[nt][od + 2]);
                }
        }

        // scores: s = cnorm - 2*dot
        const int kchunk = kslice0 + ci * CHUNK;
        float2 cn[4];
        #pragma unroll
        for (int ni = 0; ni < 4; ni++) {
            int col = kchunk + warpN * 32 + ni * 8 + q * 2;
            cn[ni] = __ldg((const float2*)(g_cnorm + col));
        }
        #pragma unroll
        for (int mi = 0; mi < 2; mi++)
            #pragma unroll
            for (int ni = 0; ni < 4; ni++) {
                acc[mi][ni][0] = fmaf(-2.0f, acc[mi][ni][0], cn[ni].x);
                acc[mi][ni][1] = fmaf(-2.0f, acc[mi][ni][1], cn[ni].y);
                acc[mi][ni][2] = fmaf(-2.0f, acc[mi][ni][2], cn[ni].x);
                acc[mi][ni][3] = fmaf(-2.0f, acc[mi][ni][3], cn[ni].y);
            }

        // per-row chunk min, running best, conditional candidate appends
        #pragma unroll
        for (int mi = 0; mi < 2; mi++) {
            #pragma unroll
            for (int h = 0; h < 2; h++) {
                float cm = 3.4e38f;
                #pragma unroll
                for (int ni = 0; ni < 4; ni++)
                    cm = fminf(cm, fminf(acc[mi][ni][2 * h], acc[mi][ni][2 * h + 1]));
                cm = fminf(cm, __shfl_xor_sync(0xFFFFFFFFu, cm, 1));
                cm = fminf(cm, __shfl_xor_sync(0xFFFFFFFFu, cm, 2));
                float rbv = fminf(rb[mi * 2 + h], cm);
                rb[mi * 2 + h] = rbv;
                float lim = rbv + THRESH;
                if (__any_sync(0xFFFFFFFFu, cm < lim)) {
                    int tok = tokBase + mi * 16 + h * 8 + g;
                    #pragma unroll
                    for (int ni = 0; ni < 4; ni++) {
                        int k0 = kchunk + warpN * 32 + ni * 8 + q * 2;
                        float s0 = acc[mi][ni][2 * h], s1 = acc[mi][ni][2 * h + 1];
                        if (s0 < lim) {
                            int sl = atomicAdd(&g_ccnt[tok], 1);
                            if (sl < CAP) g_cand[tok * CAP + sl] = k0;
                        }
                        if (s1 < lim) {
                            int sl = atomicAdd(&g_ccnt[tok], 1);
                            if (sl < CAP) g_cand[tok * CAP + sl] = k0 + 1;
                        }
                    }
                }
            }
        }
    }
}

// ---------------------------------------------------------------------------
// Pass 2: exact fp32 refine over candidates (one warp per token)
__global__ void __launch_bounds__(256)
refine_kernel(const float* __restrict__ x, const float* __restrict__ cb) {
    __shared__ float sx[8][64];
    const int wid = threadIdx.x >> 5, lane = threadIdx.x & 31;
    const int tok = blockIdx.x * 8 + wid;
    sx[wid][lane]      = x[tok * DIM + lane];
    sx[wid][lane + 32] = x[tok * DIM + 32 + lane];
    __syncwarp();

    int cnt = g_ccnt[tok];
    float bd = 3.4e38f;
    int   bi = 0x7fffffff;

    if (cnt <= CAP) {
        for (int i = lane; i < cnt; i += 32) {
            int k = g_cand[tok * CAP + i];
            const float4* cr = (const float4*)(cb + k * DIM);
            float a = 0.0f;
            #pragma unroll
            for (int j = 0; j < 16; j++) {
                float4 c4 = __ldg(cr + j);
                a = fmaf(sx[wid][4 * j],     c4.x, a);
                a = fmaf(sx[wid][4 * j + 1], c4.y, a);
                a = fmaf(sx[wid][4 * j + 2], c4.z, a);
                a = fmaf(sx[wid][4 * j + 3], c4.w, a);
            }
            float d = fmaf(-2.0f, a, g_cnorm[k]);
            if (d < bd || (d == bd && k < bi)) { bd = d; bi = k; }
        }
    } else {
        for (int k = lane; k < K_CODE; k += 32) {
            const float4* cr = (const float4*)(cb + k * DIM);
            float a = 0.0f;
            #pragma unroll
            for (int j = 0; j < 16; j++) {
                float4 c4 = __ldg(cr + j);
                a = fmaf(sx[wid][4 * j],     c4.x, a);
                a = fmaf(sx[wid][4 * j + 1], c4.y, a);
                a = fmaf(sx[wid][4 * j + 2], c4.z, a);
                a = fmaf(sx[wid][4 * j + 3], c4.w, a);
            }
            float d = fmaf(-2.0f, a, g_cnorm[k]);
            if (d < bd || (d == bd && k < bi)) { bd = d; bi = k; }
        }
    }
    #pragma unroll
    for (int off = 16; off; off >>= 1) {
        float od = __shfl_xor_sync(0xFFFFFFFFu, bd, off);
        int   oi = __shfl_xor_sync(0xFFFFFFFFu, bi, off);
        if (od < bd || (od == bd && oi < bi)) { bd = od; bi = oi; }
    }
    if (lane == 0) g_idx[tok] = bi;
}

// ---------------------------------------------------------------------------
__global__ void fill_zero_kernel(float4* __restrict__ out, size_t n4) {
    size_t i = (size_t)blockIdx.x * blockDim.x + threadIdx.x;
    size_t stride = (size_t)gridDim.x * blockDim.x;
    float4 z = make_float4(0.f, 0.f, 0.f, 0.f);
    for (; i < n4; i += stride) out[i] = z;
}

__global__ void scatter_kernel(const float* __restrict__ x,
                               const float* __restrict__ cb,
                               float* __restrict__ out) {
    int n = blockIdx.x;
    int d = threadIdx.x;
    int k = g_idx[n];
    float xv = x[n * DIM + d];
    out[OFF_QUAN + (size_t)n * DIM + d] = cb[k * DIM + d];
    atomicAdd(&g_sum[k * DIM + d], xv);
    if (d == 0) {
        atomicAdd(&g_count[k], 1.0f);
        out[(size_t)n * K_CODE + k] = 1.0f;
    }
}

__global__ void finalize_kernel(const float* __restrict__ ema_count,
                                const float* __restrict__ ema_weight,
                                float* __restrict__ out) {
    int i = blockIdx.x * blockDim.x + threadIdx.x;
    if (i < K_CODE * DIM) {
        int k = i >> 6;
        float nw = ema_weight[i] * DECAYF + g_sum[i] * OMDF;
        float nc = ema_count[k] * DECAYF + g_count[k] * OMDF;
        nc = (nc + EPSF) / (BATCHF + (float)K_CODE * EPSF) * BATCHF;
        out[OFF_WGT + i] = nw;
        out[OFF_CB  + i] = nw / nc;
        if ((i & (DIM - 1)) == 0) out[OFF_CNT + k] = nc;
    }
}

// ---------------------------------------------------------------------------
extern "C" void kernel_launch(void* const* d_in, const int* in_sizes, int n_in,
                              void* d_out, int out_size) {
    const float* x    = (const float*)d_in[0];
    const float* cb   = (const float*)d_in[1];
    const float* ecnt = (const float*)d_in[2];
    const float* ewgt = (const float*)d_in[3];
    float* out = (float*)d_out;

    // One-time side stream + events (created on first, non-captured call).
    static cudaStream_t s_side = nullptr;
    static cudaEvent_t  s_fork = nullptr, s_join = nullptr;
    if (s_side == nullptr) {
        cudaStreamCreateWithFlags(&s_side, cudaStreamNonBlocking);
        cudaEventCreateWithFlags(&s_fork, cudaEventDisableTiming);
        cudaEventCreateWithFlags(&s_join, cudaEventDisableTiming);
    }

    // Fork: zero-fill of the 536MB one-hot region on the side stream
    cudaEventRecord(s_fork, 0);
    cudaStreamWaitEvent(s_side, s_fork, 0);
    fill_zero_kernel<<<16384, 256, 0, s_side>>>((float4*)out, 33554432ULL);
    cudaEventRecord(s_join, s_side);

    // Main path
    prep_x_kernel<<<(N_TOK * DIM) / 256, 256>>>(x);
    prep_c_kernel<<<(K_CODE * DIM) / 256, 256>>>(cb);
    cnorm_kernel<<<(K_CODE * 32) / 256, 256>>>(cb);

    gemm_cand_kernel<<<128 * KSPLIT, 256, P1_SMEM>>>();
    refine_kernel<<<N_TOK / 8, 256>>>(x, cb);

    // Join: scatter writes into the zero-filled region
    cudaStreamWaitEvent(0, s_join, 0);
    scatter_kernel<<<N_TOK, DIM>>>(x, cb, out);
    finalize_kernel<<<(K_CODE * DIM) / 256, 256>>>(ecnt, ewgt, out);
}

// round 11
// speedup vs baseline: 2.0893x; 1.1923x over previous
#include <cuda_runtime.h>
#include <cuda_bf16.h>
#include <cstdint>

// Problem constants
#define N_TOK   16384
#define K_CODE  8192
#define DIM     64
#define DECAYF  0.99f
#define OMDF    0.01f
#define EPSF    1e-5f
#define BATCHF  32.0f

// Output layout (floats): concat (discrete, quantized, new_count, new_weight, new_codebook)
#define OFF_QUAN (134217728ULL)                 // N*K
#define OFF_CNT  (OFF_QUAN + 1048576ULL)        // + N*D
#define OFF_WGT  (OFF_CNT  + 8192ULL)           // + K
#define OFF_CB   (OFF_WGT  + 524288ULL)         // + K*D

#define TOK_TILE 128
#define CHUNK    64
#define KSPLIT   2
#define KSLICE   (K_CODE / KSPLIT)              // 4096
#define NCHUNK   (KSLICE / CHUNK)               // 64
#define CAP      384
#define THRESH   4.5f

// Scratch (device globals; allocation-free rule)
__device__ __align__(16) __nv_bfloat16 g_Abf[N_TOK * DIM];
__device__ __align__(16) __nv_bfloat16 g_Bbf[K_CODE * DIM];
__device__ float g_cnorm[K_CODE];
__device__ int   g_idx[N_TOK];
__device__ float g_count[K_CODE];
__device__ float g_sum[K_CODE * DIM];
__device__ int   g_ccnt[N_TOK];
__device__ int   g_cand[N_TOK * CAP];

// ---------------------------------------------------------------------------
__device__ __forceinline__ uint32_t smem_u32(const void* p) {
    uint32_t a;
    asm("{ .reg .u64 t; cvta.to.shared.u64 t, %1; cvt.u32.u64 %0, t; }" : "=r"(a) : "l"(p));
    return a;
}
__device__ __forceinline__ void cp_async16(uint32_t dst, const void* src) {
    asm volatile("cp.async.cg.shared.global [%0], [%1], 16;" :: "r"(dst), "l"(src) : "memory");
}
#define CP_COMMIT() asm volatile("cp.async.commit_group;" ::: "memory")
#define CP_WAIT(n)  asm volatile("cp.async.wait_group %0;" :: "n"(n) : "memory")

__device__ __forceinline__ void ldm_x4(uint32_t& r0, uint32_t& r1, uint32_t& r2, uint32_t& r3,
                                       uint32_t addr) {
    asm volatile("ldmatrix.sync.aligned.m8n8.x4.shared.b16 {%0,%1,%2,%3}, [%4];"
                 : "=r"(r0), "=r"(r1), "=r"(r2), "=r"(r3) : "r"(addr));
}
__device__ __forceinline__ void mma16816(float* c, const uint32_t* a, uint32_t b0, uint32_t b1) {
    asm volatile("mma.sync.aligned.m16n8k16.row.col.f32.bf16.bf16.f32 "
                 "{%0,%1,%2,%3}, {%4,%5,%6,%7}, {%8,%9}, {%0,%1,%2,%3};"
                 : "+f"(c[0]), "+f"(c[1]), "+f"(c[2]), "+f"(c[3])
                 : "r"(a[0]), "r"(a[1]), "r"(a[2]), "r"(a[3]), "r"(b0), "r"(b1));
}

// ---------------------------------------------------------------------------
// Prep kernels
__global__ void prep_x_kernel(const float* __restrict__ x) {
    int i = blockIdx.x * blockDim.x + threadIdx.x;
    if (i < N_TOK * DIM) {
        g_Abf[i] = __float2bfloat16(x[i]);
        if (i < N_TOK) g_ccnt[i] = 0;
    }
}
__global__ void prep_c_kernel(const float* __restrict__ cb) {
    int i = blockIdx.x * blockDim.x + threadIdx.x;
    if (i < K_CODE * DIM) {
        g_Bbf[i] = __float2bfloat16(cb[i]);
        g_sum[i] = 0.0f;
        if (i < K_CODE) g_count[i] = 0.0f;
    }
}
__global__ void cnorm_kernel(const float* __restrict__ cb) {
    int w = (blockIdx.x * blockDim.x + threadIdx.x) >> 5;
    int lane = threadIdx.x & 31;
    if (w < K_CODE) {
        float v0 = cb[w * DIM + lane];
        float v1 = cb[w * DIM + 32 + lane];
        float s = v0 * v0 + v1 * v1;
        #pragma unroll
        for (int o = 16; o; o >>= 1) s += __shfl_xor_sync(0xFFFFFFFFu, s, o);
        if (lane == 0) g_cnorm[w] = s;
    }
}

// ---------------------------------------------------------------------------
// Pass 1: barrier-free HMMA GEMM + approx argmin band -> candidate lists.
// Grid = 128 token-blocks x 2 K-slices = 256 CTAs, 256 thr (8 warps = 4M x 2N).
// Warp tile 32x32. A fragments resident in registers (loaded once from gmem).
// B: per-warp private 3-slot cp.async ring (4KB/slot) -> NO __syncthreads in loop.
#define B_SLOT  4096
#define P1_SMEM (8 * 3 * B_SLOT)   // 96KB -> 2 CTAs/SM

__device__ __forceinline__ uint32_t sw_off(int row, int c) {
    return (uint32_t)(row * 128 + ((c ^ (row & 7)) << 4));
}

// Per-warp prefetch of its own 32-row B sub-tile (4KB): 8 cp.async per lane
__device__ __forceinline__ void prefetch_B_warp(uint32_t dst, int krow0, int lane) {
    const char* src = (const char*)(g_Bbf) + (size_t)krow0 * 128;
    #pragma unroll
    for (int t = 0; t < 8; t++) {
        int j = lane + t * 32;          // 0..255 16B-chunks
        int row = j >> 3, c = j & 7;
        cp_async16(dst + sw_off(row, c), src + row * 128 + c * 16);
    }
    CP_COMMIT();
}

extern "C" __global__ void __launch_bounds__(256, 2)
gemm_cand_kernel() {
    extern __shared__ unsigned char smem[];
    const uint32_t sbase = smem_u32(smem);
    const int tid   = threadIdx.x;
    const int wid   = tid >> 5;
    const int lane  = tid & 31;
    const int warpM = wid >> 1;          // 0..3
    const int warpN = wid & 1;           // 0..1
    const int g     = lane >> 2;         // row group 0..7
    const int q     = lane & 3;          // col group 0..3
    const int lr    = lane & 15;
    const int lc    = lane >> 4;
    const int tb    = blockIdx.x & 127;             // token block
    const int slice = blockIdx.x >> 7;              // k slice 0..1
    const int kslice0 = slice * KSLICE;
    const int tokBase = tb * TOK_TILE + warpM * 32;
    const uint32_t ring = sbase + (uint32_t)(wid * 3) * B_SLOT;

    // Prolog: prefetch my B rows for chunks 0,1
    prefetch_B_warp(ring,          kslice0 + warpN * 32,         lane);
    prefetch_B_warp(ring + B_SLOT, kslice0 + CHUNK + warpN * 32, lane);

    // A fragments: resident in registers for all 64 chunks.
    // m16n8k16 A-frag mapping: a0=(r,c) a1=(r+8,c) a2=(r,c+8) a3=(r+8,c+8),
    // r = lane>>2, c = (lane&3)*2 within the 16x16 (mi,ks) tile.
    uint32_t afrag[2][4][4];
    {
        const __nv_bfloat16* Ab = g_Abf + (size_t)(tb * TOK_TILE) * DIM;
        #pragma unroll
        for (int mi = 0; mi < 2; mi++)
            #pragma unroll
            for (int ks = 0; ks < 4; ks++) {
                int R = warpM * 32 + mi * 16 + (lane >> 2);
                int C = ks * 16 + (lane & 3) * 2;
                afrag[mi][ks][0] = *(const uint32_t*)(Ab + (size_t)R * DIM + C);
                afrag[mi][ks][1] = *(const uint32_t*)(Ab + (size_t)(R + 8) * DIM + C);
                afrag[mi][ks][2] = *(const uint32_t*)(Ab + (size_t)R * DIM + C + 8);
                afrag[mi][ks][3] = *(const uint32_t*)(Ab + (size_t)(R + 8) * DIM + C + 8);
            }
    }

    float rb[4] = {3.4e38f, 3.4e38f, 3.4e38f, 3.4e38f};

    for (int ci = 0; ci < NCHUNK; ci++) {
        // Keep group-count invariant: always commit exactly one group per iter
        if (ci + 2 < NCHUNK)
            prefetch_B_warp(ring + ((ci + 2) % 3) * B_SLOT,
                            kslice0 + (ci + 2) * CHUNK + warpN * 32, lane);
        else
            CP_COMMIT();
        CP_WAIT(2);          // chunk ci's data complete (per-thread groups)
        __syncwarp();        // cross-lane smem visibility within the warp

        const uint32_t Bs = ring + (ci % 3) * B_SLOT;

        float acc[2][4][4];
        #pragma unroll
        for (int mi = 0; mi < 2; mi++)
            #pragma unroll
            for (int ni = 0; ni < 4; ni++)
                #pragma unroll
                for (int t = 0; t < 4; t++) acc[mi][ni][t] = 0.0f;

        #pragma unroll
        for (int ks = 0; ks < 4; ks++) {
            uint32_t b[2][4];
            #pragma unroll
            for (int nt = 0; nt < 2; nt++) {
                int row = nt * 16 + lr;             // local row in my 32-row tile
                ldm_x4(b[nt][0], b[nt][1], b[nt][2], b[nt][3],
                       Bs + sw_off(row, ks * 2 + lc));
            }
            #pragma unroll
            for (int mi = 0; mi < 2; mi++)
                #pragma unroll
                for (int ni = 0; ni < 4; ni++) {
                    int nt = ni >> 1, od = ni & 1;
                    mma16816(acc[mi][ni], afrag[mi][ks], b[nt][od], b[nt][od + 2]);
                }
        }

        // scores: s = cnorm - 2*dot
        const int kchunk = kslice0 + ci * CHUNK;
        float2 cn[4];
        #pragma unroll
        for (int ni = 0; ni < 4; ni++) {
            int col = kchunk + warpN * 32 + ni * 8 + q * 2;
            cn[ni] = __ldg((const float2*)(g_cnorm + col));
        }
        #pragma unroll
        for (int mi = 0; mi < 2; mi++)
            #pragma unroll
            for (int ni = 0; ni < 4; ni++) {
                acc[mi][ni][0] = fmaf(-2.0f, acc[mi][ni][0], cn[ni].x);
                acc[mi][ni][1] = fmaf(-2.0f, acc[mi][ni][1], cn[ni].y);
                acc[mi][ni][2] = fmaf(-2.0f, acc[mi][ni][2], cn[ni].x);
                acc[mi][ni][3] = fmaf(-2.0f, acc[mi][ni][3], cn[ni].y);
            }

        // per-row chunk min, running best, conditional candidate appends
        #pragma unroll
        for (int mi = 0; mi < 2; mi++) {
            #pragma unroll
            for (int h = 0; h < 2; h++) {
                float cm = 3.4e38f;
                #pragma unroll
                for (int ni = 0; ni < 4; ni++)
                    cm = fminf(cm, fminf(acc[mi][ni][2 * h], acc[mi][ni][2 * h + 1]));
                cm = fminf(cm, __shfl_xor_sync(0xFFFFFFFFu, cm, 1));
                cm = fminf(cm, __shfl_xor_sync(0xFFFFFFFFu, cm, 2));
                float rbv = fminf(rb[mi * 2 + h], cm);
                rb[mi * 2 + h] = rbv;
                float lim = rbv + THRESH;
                if (__any_sync(0xFFFFFFFFu, cm < lim)) {
                    int tok = tokBase + mi * 16 + h * 8 + g;
                    #pragma unroll
                    for (int ni = 0; ni < 4; ni++) {
                        int k0 = kchunk + warpN * 32 + ni * 8 + q * 2;
                        float s0 = acc[mi][ni][2 * h], s1 = acc[mi][ni][2 * h + 1];
                        if (s0 < lim) {
                            int sl = atomicAdd(&g_ccnt[tok], 1);
                            if (sl < CAP) g_cand[tok * CAP + sl] = k0;
                        }
                        if (s1 < lim) {
                            int sl = atomicAdd(&g_ccnt[tok], 1);
                            if (sl < CAP) g_cand[tok * CAP + sl] = k0 + 1;
                        }
                    }
                }
            }
        }
    }
}

// ---------------------------------------------------------------------------
// Pass 2: exact fp32 refine over candidates (one warp per token)
__global__ void __launch_bounds__(256)
refine_kernel(const float* __restrict__ x, const float* __restrict__ cb) {
    __shared__ float sx[8][64];
    const int wid = threadIdx.x >> 5, lane = threadIdx.x & 31;
    const int tok = blockIdx.x * 8 + wid;
    sx[wid][lane]      = x[tok * DIM + lane];
    sx[wid][lane + 32] = x[tok * DIM + 32 + lane];
    __syncwarp();

    int cnt = g_ccnt[tok];
    float bd = 3.4e38f;
    int   bi = 0x7fffffff;

    if (cnt <= CAP) {
        for (int i = lane; i < cnt; i += 32) {
            int k = g_cand[tok * CAP + i];
            const float4* cr = (const float4*)(cb + k * DIM);
            float a = 0.0f;
            #pragma unroll
            for (int j = 0; j < 16; j++) {
                float4 c4 = __ldg(cr + j);
                a = fmaf(sx[wid][4 * j],     c4.x, a);
                a = fmaf(sx[wid][4 * j + 1], c4.y, a);
                a = fmaf(sx[wid][4 * j + 2], c4.z, a);
                a = fmaf(sx[wid][4 * j + 3], c4.w, a);
            }
            float d = fmaf(-2.0f, a, g_cnorm[k]);
            if (d < bd || (d == bd && k < bi)) { bd = d; bi = k; }
        }
    } else {
        for (int k = lane; k < K_CODE; k += 32) {
            const float4* cr = (const float4*)(cb + k * DIM);
            float a = 0.0f;
            #pragma unroll
            for (int j = 0; j < 16; j++) {
                float4 c4 = __ldg(cr + j);
                a = fmaf(sx[wid][4 * j],     c4.x, a);
                a = fmaf(sx[wid][4 * j + 1], c4.y, a);
                a = fmaf(sx[wid][4 * j + 2], c4.z, a);
                a = fmaf(sx[wid][4 * j + 3], c4.w, a);
            }
            float d = fmaf(-2.0f, a, g_cnorm[k]);
            if (d < bd || (d == bd && k < bi)) { bd = d; bi = k; }
        }
    }
    #pragma unroll
    for (int off = 16; off; off >>= 1) {
        float od = __shfl_xor_sync(0xFFFFFFFFu, bd, off);
        int   oi = __shfl_xor_sync(0xFFFFFFFFu, bi, off);
        if (od < bd || (od == bd && oi < bi)) { bd = od; bi = oi; }
    }
    if (lane == 0) g_idx[tok] = bi;
}

// ---------------------------------------------------------------------------
__global__ void fill_zero_kernel(float4* __restrict__ out, size_t n4) {
    size_t i = (size_t)blockIdx.x * blockDim.x + threadIdx.x;
    size_t stride = (size_t)gridDim.x * blockDim.x;
    float4 z = make_float4(0.f, 0.f, 0.f, 0.f);
    for (; i < n4; i += stride) out[i] = z;
}

__global__ void scatter_kernel(const float* __restrict__ x,
                               const float* __restrict__ cb,
                               float* __restrict__ out) {
    int n = blockIdx.x;
    int d = threadIdx.x;
    int k = g_idx[n];
    float xv = x[n * DIM + d];
    out[OFF_QUAN + (size_t)n * DIM + d] = cb[k * DIM + d];
    atomicAdd(&g_sum[k * DIM + d], xv);
    if (d == 0) {
        atomicAdd(&g_count[k], 1.0f);
        out[(size_t)n * K_CODE + k] = 1.0f;
    }
}

__global__ void finalize_kernel(const float* __restrict__ ema_count,
                                const float* __restrict__ ema_weight,
                                float* __restrict__ out) {
    int i = blockIdx.x * blockDim.x + threadIdx.x;
    if (i < K_CODE * DIM) {
        int k = i >> 6;
        float nw = ema_weight[i] * DECAYF + g_sum[i] * OMDF;
        float nc = ema_count[k] * DECAYF + g_count[k] * OMDF;
        nc = (nc + EPSF) / (BATCHF + (float)K_CODE * EPSF) * BATCHF;
        out[OFF_WGT + i] = nw;
        out[OFF_CB  + i] = nw / nc;
        if ((i & (DIM - 1)) == 0) out[OFF_CNT + k] = nc;
    }
}

// ---------------------------------------------------------------------------
extern "C" void kernel_launch(void* const* d_in, const int* in_sizes, int n_in,
                              void* d_out, int out_size) {
    const float* x    = (const float*)d_in[0];
    const float* cb   = (const float*)d_in[1];
    const float* ecnt = (const float*)d_in[2];
    const float* ewgt = (const float*)d_in[3];
    float* out = (float*)d_out;

    // One-time side stream + events (created on first, non-captured call).
    static cudaStream_t s_side = nullptr;
    static cudaEvent_t  s_fork = nullptr, s_join = nullptr;
    if (s_side == nullptr) {
        cudaStreamCreateWithFlags(&s_side, cudaStreamNonBlocking);
        cudaEventCreateWithFlags(&s_fork, cudaEventDisableTiming);
        cudaEventCreateWithFlags(&s_join, cudaEventDisableTiming);
    }

    cudaFuncSetAttribute(gemm_cand_kernel,
                         cudaFuncAttributeMaxDynamicSharedMemorySize, P1_SMEM);

    // Fork: zero-fill of the 536MB one-hot region on the side stream
    cudaEventRecord(s_fork, 0);
    cudaStreamWaitEvent(s_side, s_fork, 0);
    fill_zero_kernel<<<16384, 256, 0, s_side>>>((float4*)out, 33554432ULL);
    cudaEventRecord(s_join, s_side);

    // Main path
    prep_x_kernel<<<(N_TOK * DIM) / 256, 256>>>(x);
    prep_c_kernel<<<(K_CODE * DIM) / 256, 256>>>(cb);
    cnorm_kernel<<<(K_CODE * 32) / 256, 256>>>(cb);

    gemm_cand_kernel<<<128 * KSPLIT, 256, P1_SMEM>>>();
    refine_kernel<<<N_TOK / 8, 256>>>(x, cb);

    // Join: scatter writes into the zero-filled region
    cudaStreamWaitEvent(0, s_join, 0);
    scatter_kernel<<<N_TOK, DIM>>>(x, cb, out);
    finalize_kernel<<<(K_CODE * DIM) / 256, 256>>>(ecnt, ewgt, out);
}